// round 12
// baseline (speedup 1.0000x reference)
#include <cuda_runtime.h>
#include <cuda_fp16.h>
#include <math.h>
#include <stdint.h>

// ---------------------------------------------------------------------------
// Problem constants (fixed shapes)
// ---------------------------------------------------------------------------
#define Bb     2
#define Ll     2048
#define Dm     1024
#define Hh     32
#define Pp     64
#define Nn     128
#define KCONV  4
#define Ck     256
#define Nc     8          // Ll / Ck
#define Inter  2048
#define ConvD  2304
#define ProjD  4384
#define BL     (Bb * Ll)  // 4096

// ---------------------------------------------------------------------------
// Scratch (device globals; no dynamic allocation allowed)
// ---------------------------------------------------------------------------
__device__ float g_proj[(size_t)BL * ProjD];
__device__ float g_conv[(size_t)BL * ConvD];
__device__ float g_dtv[(size_t)BL * Hh];
__device__ float g_acum[(size_t)Bb * Nc * Hh * Ck];
__device__ float g_gm[(size_t)Bb * Nc * Ck * Ck];
__device__ float g_y[(size_t)BL * Inter];
__device__ float g_states[(size_t)Bb * Nc * Hh * Pp * Nn];
__device__ float g_prev[(size_t)Bb * Nc * Hh * Pp * Nn];

// fp16 buffers
__device__ __half g_Ah[(size_t)BL * Inter];
__device__ __half g_Bh[(size_t)ProjD * Dm];

__device__ __forceinline__ float siluf(float x) { return x / (1.f + expf(-x)); }

__device__ __forceinline__ float4 ldg4(const float* p) {
    return *reinterpret_cast<const float4*>(p);
}

// ---------------------------------------------------------------------------
// PTX helpers
// ---------------------------------------------------------------------------
__device__ __forceinline__ unsigned su32(const void* p) {
    return (unsigned)__cvta_generic_to_shared(p);
}

__device__ __forceinline__ void cp16(unsigned dst, const void* src, bool ok) {
    int sz = ok ? 16 : 0;
    asm volatile("cp.async.cg.shared.global [%0], [%1], 16, %2;\n"
                 :: "r"(dst), "l"(src), "r"(sz));
}

__device__ __forceinline__ void ldsm4(unsigned& r0, unsigned& r1, unsigned& r2, unsigned& r3,
                                      unsigned addr) {
    asm volatile("ldmatrix.sync.aligned.m8n8.x4.shared.b16 {%0,%1,%2,%3}, [%4];"
                 : "=r"(r0), "=r"(r1), "=r"(r2), "=r"(r3) : "r"(addr));
}

__device__ __forceinline__ void mma16816(float* c, const unsigned* a, const unsigned* b) {
    asm volatile(
        "mma.sync.aligned.m16n8k16.row.col.f32.f16.f16.f32 "
        "{%0,%1,%2,%3}, {%4,%5,%6,%7}, {%8,%9}, {%0,%1,%2,%3};"
        : "+f"(c[0]), "+f"(c[1]), "+f"(c[2]), "+f"(c[3])
        : "r"(a[0]), "r"(a[1]), "r"(a[2]), "r"(a[3]), "r"(b[0]), "r"(b[1]));
}

// ---------------------------------------------------------------------------
// Tensor-core fp16 GEMM, 1-pass: C = Ah*Bh, fp32 accum. (unchanged)
// ---------------------------------------------------------------------------
#define GEMM_SMEM (2 * 36864)

struct Frags {
    unsigned ah[4][4];
    unsigned bh[4][2];
};

__device__ __forceinline__ void load_frags(Frags& F, unsigned stg, int ks,
                                           int wm, int wn, int lane) {
    const int rA = lane & 15;
    const int cB = ((lane >> 4) << 4);
    const unsigned colb = (unsigned)(ks * 32 + cB);
#pragma unroll
    for (int mf = 0; mf < 4; mf++) {
        unsigned ra = stg + (wm * 64 + mf * 16 + rA) * 144 + colb;
        ldsm4(F.ah[mf][0], F.ah[mf][1], F.ah[mf][2], F.ah[mf][3], ra);
    }
#pragma unroll
    for (int nf2 = 0; nf2 < 2; nf2++) {
        unsigned rb = stg + 18432 + (wn * 32 + nf2 * 16 + rA) * 144 + colb;
        unsigned t0, t1, t2, t3;
        ldsm4(t0, t1, t2, t3, rb);
        F.bh[nf2 * 2][0] = t0; F.bh[nf2 * 2][1] = t2;
        F.bh[nf2 * 2 + 1][0] = t1; F.bh[nf2 * 2 + 1][1] = t3;
    }
}

__device__ __forceinline__ void gemm_core(const __half* __restrict__ Ah,
                                          const __half* __restrict__ Bh,
                                          float* __restrict__ C,
                                          int M, int N, int K) {
    extern __shared__ char dyn[];
    const unsigned sbase = su32(dyn);
    const int tid = threadIdx.x;
    const int lane = tid & 31;
    const int warp = tid >> 5;
    const int wm = warp >> 2;
    const int wn = warp & 3;
    const int m0 = blockIdx.y * 128;
    const int n0 = blockIdx.x * 128;
    const int KB = K >> 6;

    float acc[4][4][4];
#pragma unroll
    for (int a = 0; a < 4; a++)
#pragma unroll
        for (int b = 0; b < 4; b++)
#pragma unroll
            for (int c = 0; c < 4; c++) acc[a][b][c] = 0.f;

    auto issue = [&](int kc, int st) {
        unsigned stg = sbase + st * 36864;
#pragma unroll
        for (int i = 0; i < 8; i++) {
            int q = tid + (i << 8);
            int mat = q >> 10;
            int r = (q >> 3) & 127;
            int c16 = q & 7;
            const __half* base = mat ? Bh : Ah;
            int gr = (mat ? n0 : m0) + r;
            bool ok = gr < (mat ? N : M);
            if (!ok) gr = (mat ? N : M) - 1;
            const void* src = base + (size_t)gr * K + (kc << 6) + (c16 << 3);
            unsigned dst = stg + mat * 18432 + r * 144 + (c16 << 4);
            cp16(dst, src, ok);
        }
        asm volatile("cp.async.commit_group;\n");
    };

    issue(0, 0);
    if (KB > 1) issue(1, 1);

    Frags F[2];

    for (int kb = 0; kb < KB; kb++) {
        int st = kb & 1;
        if (kb + 1 < KB) asm volatile("cp.async.wait_group 1;\n");
        else             asm volatile("cp.async.wait_group 0;\n");
        __syncthreads();
        unsigned stg = sbase + st * 36864;

        load_frags(F[0], stg, 0, wm, wn, lane);
#pragma unroll
        for (int ks = 0; ks < 4; ks++) {
            if (ks < 3) load_frags(F[(ks + 1) & 1], stg, ks + 1, wm, wn, lane);
            Frags& f = F[ks & 1];
#pragma unroll
            for (int mf = 0; mf < 4; mf++)
#pragma unroll
                for (int nf = 0; nf < 4; nf++)
                    mma16816(acc[mf][nf], f.ah[mf], f.bh[nf]);
        }
        __syncthreads();
        if (kb + 2 < KB) issue(kb + 2, st);
    }

    int g4 = lane >> 2, t4 = lane & 3;
#pragma unroll
    for (int mf = 0; mf < 4; mf++) {
        int r0 = m0 + wm * 64 + mf * 16 + g4;
#pragma unroll
        for (int nf = 0; nf < 4; nf++) {
            int cg = n0 + wn * 32 + nf * 8 + t4 * 2;
            if (cg < N) {
                float* p0 = C + (size_t)r0 * N + cg;
                p0[0] = acc[mf][nf][0];
                p0[1] = acc[mf][nf][1];
                float* p1 = p0 + (size_t)8 * N;
                p1[0] = acc[mf][nf][2];
                p1[1] = acc[mf][nf][3];
            }
        }
    }
}

__global__ __launch_bounds__(256) void gemm_in_kernel() {
    gemm_core(g_Ah, g_Bh, g_proj, BL, ProjD, Dm);
}

__global__ __launch_bounds__(256) void gemm_out_kernel(float* __restrict__ out) {
    gemm_core(g_Ah, g_Bh, out, BL, Dm, Inter);
}

// ---------------------------------------------------------------------------
// fp16 conversions
// ---------------------------------------------------------------------------
__global__ void round_x_kernel(const float* __restrict__ in, int n) {
    int i = blockIdx.x * blockDim.x + threadIdx.x;
    if (i >= n) return;
    g_Ah[i] = __float2half(in[i]);
}

__global__ void round_w_kernel(const float* __restrict__ in, int n) {
    int i = blockIdx.x * blockDim.x + threadIdx.x;
    if (i >= n) return;
    g_Bh[i] = __float2half(in[i]);
}

// ---------------------------------------------------------------------------
// Depthwise causal conv1d + SiLU (sliding window, 32 positions/thread)
// ---------------------------------------------------------------------------
__global__ __launch_bounds__(256) void conv_silu_kernel(const float* __restrict__ cw,
                                                        const float* __restrict__ cb) {
    int ch = blockIdx.x * 256 + threadIdx.x;
    int l0 = blockIdx.y * 32;
    int b  = blockIdx.z;
    const float* col = g_proj + (size_t)b * Ll * ProjD + Inter + ch;
    float w0 = cw[ch * KCONV + 0];
    float w1 = cw[ch * KCONV + 1];
    float w2 = cw[ch * KCONV + 2];
    float w3 = cw[ch * KCONV + 3];
    float bias = cb[ch];
    float xm3 = (l0 >= 3) ? col[(size_t)(l0 - 3) * ProjD] : 0.f;
    float xm2 = (l0 >= 2) ? col[(size_t)(l0 - 2) * ProjD] : 0.f;
    float xm1 = (l0 >= 1) ? col[(size_t)(l0 - 1) * ProjD] : 0.f;
    float* outp = g_conv + (size_t)(b * Ll + l0) * ConvD + ch;
#pragma unroll 4
    for (int i = 0; i < 32; i++) {
        float x0 = col[(size_t)(l0 + i) * ProjD];
        float acc = bias + w0 * xm3 + w1 * xm2 + w2 * xm1 + w3 * x0;
        outp[(size_t)i * ConvD] = siluf(acc);
        xm3 = xm2; xm2 = xm1; xm1 = x0;
    }
}

// ---------------------------------------------------------------------------
// Per-chunk inclusive cumsum of dt * A with fused softplus
// ---------------------------------------------------------------------------
__global__ void acum_kernel(const float* __restrict__ A_log,
                            const float* __restrict__ dt_bias) {
    int blk = blockIdx.x;
    int h = blk % Hh;
    int bc = blk / Hh;
    int b = bc / Nc, c = bc % Nc;
    int t = threadIdx.x;
    float A = -expf(A_log[h]);
    int bl = b * Ll + c * Ck + t;
    float raw = g_proj[(size_t)bl * ProjD + Inter + ConvD + h] + dt_bias[h];
    float dt = (raw > 20.f) ? raw : log1pf(expf(raw));
    g_dtv[(size_t)bl * Hh + h] = dt;
    float v = dt * A;
    __shared__ float s[Ck];
    s[t] = v;
    __syncthreads();
    for (int off = 1; off < Ck; off <<= 1) {
        float x = (t >= off) ? s[t - off] : 0.f;
        __syncthreads();
        s[t] += x;
        __syncthreads();
    }
    g_acum[(size_t)blk * Ck + t] = s[t];
}

// ---------------------------------------------------------------------------
// gm (fp16 mma): Gm[s,z] = sum_n C[s,n]*B[z,n], 64x64x128 tiles, lower tri.
// smem stride 272 B (conflict-free ldmatrix). 8 warps 2(m) x 4(n), warp 32x16.
// ---------------------------------------------------------------------------
__global__ __launch_bounds__(256) void gm_kernel() {
    int bc = blockIdx.x;
    int sT = blockIdx.y, zT = blockIdx.z;
    if (zT > sT) return;
    int b = bc / Nc, c = bc % Nc;
    int rowbase = b * Ll + c * Ck;
    __shared__ __align__(16) __half Cs[64][136];
    __shared__ __align__(16) __half Bs[64][136];
    int tid = threadIdx.x;
    int lane = tid & 31;
    int warp = tid >> 5;
    int wm = warp >> 2;   // 0..1
    int wn = warp & 3;    // 0..3

    // fill: convert fp32 g_conv -> fp16 smem (8 float4-groups per thread per mat)
#pragma unroll
    for (int i = 0; i < 8; i++) {
        int q = tid + (i << 8);       // 0..2047 groups of 4
        int row = q >> 5;
        int c4 = (q & 31) * 4;
        float4 vc = ldg4(g_conv + (size_t)(rowbase + sT * 64 + row) * ConvD + Inter + Nn + c4);
        *(half2*)&Cs[row][c4]     = __floats2half2_rn(vc.x, vc.y);
        *(half2*)&Cs[row][c4 + 2] = __floats2half2_rn(vc.z, vc.w);
        float4 vb = ldg4(g_conv + (size_t)(rowbase + zT * 64 + row) * ConvD + Inter + c4);
        *(half2*)&Bs[row][c4]     = __floats2half2_rn(vb.x, vb.y);
        *(half2*)&Bs[row][c4 + 2] = __floats2half2_rn(vb.z, vb.w);
    }
    __syncthreads();

    const unsigned cbase = su32(Cs);
    const unsigned bbase = su32(Bs);
    float acc[2][2][4];
#pragma unroll
    for (int i = 0; i < 2; i++)
#pragma unroll
        for (int j = 0; j < 2; j++)
#pragma unroll
            for (int k = 0; k < 4; k++) acc[i][j][k] = 0.f;

    const int rA = lane & 15;
    const int cB = (lane >> 4) << 4;   // bytes
#pragma unroll
    for (int ks = 0; ks < 8; ks++) {
        unsigned colb = (unsigned)(ks * 32 + cB);
        unsigned a[2][4], bb[2][2];
#pragma unroll
        for (int mf = 0; mf < 2; mf++) {
            unsigned ra = cbase + (wm * 32 + mf * 16 + rA) * 272 + colb;
            ldsm4(a[mf][0], a[mf][1], a[mf][2], a[mf][3], ra);
        }
        {
            unsigned rb = bbase + (wn * 16 + rA) * 272 + colb;
            unsigned t0, t1, t2, t3;
            ldsm4(t0, t1, t2, t3, rb);
            bb[0][0] = t0; bb[0][1] = t2;
            bb[1][0] = t1; bb[1][1] = t3;
        }
#pragma unroll
        for (int mf = 0; mf < 2; mf++)
#pragma unroll
            for (int nf = 0; nf < 2; nf++)
                mma16816(acc[mf][nf], a[mf], bb[nf]);
    }

    int g4 = lane >> 2, t4 = lane & 3;
#pragma unroll
    for (int mf = 0; mf < 2; mf++) {
#pragma unroll
        for (int nf = 0; nf < 2; nf++) {
            int sg = sT * 64 + wm * 32 + mf * 16 + g4;
            int zg = zT * 64 + wn * 16 + nf * 8 + t4 * 2;
            float* pg = g_gm + ((size_t)bc * Ck + sg) * Ck + zg;
            pg[0] = acc[mf][nf][0];
            pg[1] = acc[mf][nf][1];
            float* pg1 = pg + (size_t)8 * Ck;
            pg1[0] = acc[mf][nf][2];
            pg1[1] = acc[mf][nf][3];
        }
    }
}

// ---------------------------------------------------------------------------
// Y_diag — fp32 (unchanged from R11)
// ---------------------------------------------------------------------------
__global__ __launch_bounds__(256) void ydiag_kernel() {
    int bc = blockIdx.x;
    int h = blockIdx.y;
    int sT = blockIdx.z;
    int b = bc / Nc, c = bc % Nc;
    int tid = threadIdx.x;
    int ty = tid >> 4, tx = tid & 15;

    __shared__ float Ms[64][65];
    __shared__ __align__(16) float Hs[64][68];
    __shared__ float sAc[64], zAc[64], ezs[64];

    const float* acumC = g_acum + ((size_t)bc * Hh + h) * Ck;
    if (tid < 64) sAc[tid] = acumC[sT * 64 + tid];
    int rowbase = b * Ll + c * Ck;

    float acc[4][4];
#pragma unroll
    for (int i = 0; i < 4; i++)
#pragma unroll
        for (int j = 0; j < 4; j++) acc[i][j] = 0.f;

    for (int zT = 0; zT <= sT; zT++) {
        float M = acumC[zT * 64 + 63];
        if (tid < 64) {
            float az = acumC[zT * 64 + tid];
            zAc[tid] = az;
            ezs[tid] = expf(M - az);
        }
        {
            int zz = tid >> 2;
            int p0 = (tid & 3) * 16;
            int l = rowbase + zT * 64 + zz;
            float d = g_dtv[(size_t)l * Hh + h];
            const float* ph = g_conv + (size_t)l * ConvD + h * Pp + p0;
#pragma unroll
            for (int u = 0; u < 4; u++) {
                float4 v = ldg4(ph + u * 4);
                *reinterpret_cast<float4*>(&Hs[zz][p0 + u * 4]) =
                    make_float4(v.x * d, v.y * d, v.z * d, v.w * d);
            }
        }
        __syncthreads();
        {
            int zz4 = (tid & 15) * 4;
            int ss4 = (tid >> 4) * 4;
            if (zT < sT) {
#pragma unroll
                for (int a = 0; a < 4; a++) {
                    int ss = ss4 + a;
                    int sg = sT * 64 + ss;
                    float es = expf(sAc[ss] - M);
                    float4 g = ldg4(g_gm + ((size_t)bc * Ck + sg) * Ck + zT * 64 + zz4);
                    Ms[zz4 + 0][ss] = g.x * ezs[zz4 + 0] * es;
                    Ms[zz4 + 1][ss] = g.y * ezs[zz4 + 1] * es;
                    Ms[zz4 + 2][ss] = g.z * ezs[zz4 + 2] * es;
                    Ms[zz4 + 3][ss] = g.w * ezs[zz4 + 3] * es;
                }
            } else {
#pragma unroll
                for (int a = 0; a < 4; a++) {
                    int ss = ss4 + a;
                    int sg = sT * 64 + ss;
                    float as = sAc[ss];
                    float4 g = ldg4(g_gm + ((size_t)bc * Ck + sg) * Ck + zT * 64 + zz4);
                    float gv[4] = {g.x, g.y, g.z, g.w};
#pragma unroll
                    for (int q = 0; q < 4; q++) {
                        int zz = zz4 + q;
                        float m = 0.f;
                        if ((zT * 64 + zz) <= sg)
                            m = gv[q] * expf(as - zAc[zz]);
                        Ms[zz][ss] = m;
                    }
                }
            }
        }
        __syncthreads();
#pragma unroll 4
        for (int zz = 0; zz < 64; zz++) {
            float rm[4];
#pragma unroll
            for (int i = 0; i < 4; i++) rm[i] = Ms[zz][ty * 4 + i];
            float4 rh = *(const float4*)&Hs[zz][tx * 4];
            float rhv[4] = {rh.x, rh.y, rh.z, rh.w};
#pragma unroll
            for (int i = 0; i < 4; i++)
#pragma unroll
                for (int j = 0; j < 4; j++) acc[i][j] += rm[i] * rhv[j];
        }
        __syncthreads();
    }
#pragma unroll
    for (int i = 0; i < 4; i++) {
        int l = rowbase + sT * 64 + ty * 4 + i;
        float* py = g_y + (size_t)l * Inter + h * Pp + tx * 4;
        *reinterpret_cast<float4*>(py) = make_float4(acc[i][0], acc[i][1], acc[i][2], acc[i][3]);
    }
}

// ---------------------------------------------------------------------------
// states — fp32 (unchanged from R11)
// ---------------------------------------------------------------------------
__global__ __launch_bounds__(256) void states_kernel() {
    int bc = blockIdx.x, h = blockIdx.y;
    int b = bc / Nc, c = bc % Nc;
    int tid = threadIdx.x;
    int ty = tid >> 4, tx = tid & 15;
    __shared__ __align__(16) float Hd[32][68];
    __shared__ __align__(16) float Bsm[32][132];
    const float* acumC = g_acum + ((size_t)bc * Hh + h) * Ck;
    float aLast = acumC[Ck - 1];
    int rowbase = b * Ll + c * Ck;
    float acc[4][8];
#pragma unroll
    for (int i = 0; i < 4; i++)
#pragma unroll
        for (int j = 0; j < 8; j++) acc[i][j] = 0.f;

    for (int l0 = 0; l0 < Ck; l0 += 32) {
        {
            int ll = tid >> 3;
            int p0 = (tid & 7) * 8;
            int l = rowbase + l0 + ll;
            float w = g_dtv[(size_t)l * Hh + h] * expf(aLast - acumC[l0 + ll]);
            const float* ph = g_conv + (size_t)l * ConvD + h * Pp + p0;
#pragma unroll
            for (int u = 0; u < 2; u++) {
                float4 v = ldg4(ph + u * 4);
                *reinterpret_cast<float4*>(&Hd[ll][p0 + u * 4]) =
                    make_float4(v.x * w, v.y * w, v.z * w, v.w * w);
            }
        }
        {
            int ll = tid >> 3;
            int n0v = (tid & 7) * 16;
            const float* pb = g_conv + (size_t)(rowbase + l0 + ll) * ConvD + Inter + n0v;
#pragma unroll
            for (int u = 0; u < 4; u++)
                *reinterpret_cast<float4*>(&Bsm[ll][n0v + u * 4]) = ldg4(pb + u * 4);
        }
        __syncthreads();
#pragma unroll 4
        for (int ll = 0; ll < 32; ll++) {
            float4 rh4 = *(const float4*)&Hd[ll][ty * 4];
            float4 rb0 = *(const float4*)&Bsm[ll][tx * 8];
            float4 rb1 = *(const float4*)&Bsm[ll][tx * 8 + 4];
            float rh[4] = {rh4.x, rh4.y, rh4.z, rh4.w};
            float rb[8] = {rb0.x, rb0.y, rb0.z, rb0.w, rb1.x, rb1.y, rb1.z, rb1.w};
#pragma unroll
            for (int i = 0; i < 4; i++)
#pragma unroll
                for (int j = 0; j < 8; j++) acc[i][j] += rh[i] * rb[j];
        }
        __syncthreads();
    }
    float* ps = g_states + ((size_t)bc * Hh + h) * Pp * Nn;
#pragma unroll
    for (int i = 0; i < 4; i++) {
        float* p = ps + (ty * 4 + i) * Nn + tx * 8;
        *reinterpret_cast<float4*>(p) = make_float4(acc[i][0], acc[i][1], acc[i][2], acc[i][3]);
        *reinterpret_cast<float4*>(p + 4) = make_float4(acc[i][4], acc[i][5], acc[i][6], acc[i][7]);
    }
}

// ---------------------------------------------------------------------------
// Inter-chunk recurrence
// ---------------------------------------------------------------------------
__global__ void prev_kernel() {
    int idx = blockIdx.x * blockDim.x + threadIdx.x;
    if (idx >= Bb * Hh * Pp * Nn) return;
    int n = idx % Nn;
    int p = (idx / Nn) % Pp;
    int h = (idx / (Nn * Pp)) % Hh;
    int b = idx / (Nn * Pp * Hh);
    float r = 0.f;
    for (int c = 0; c < Nc; c++) {
        size_t off = (((size_t)(b * Nc + c) * Hh + h) * Pp + p) * Nn + n;
        g_prev[off] = r;
        float zl = g_acum[((size_t)(b * Nc + c) * Hh + h) * Ck + (Ck - 1)];
        r = g_states[off] + expf(zl) * r;
    }
}

// ---------------------------------------------------------------------------
// Y_off (fp16 mma): Y_off[l,p] = sum_n C[l,n]*prev[p,n]; combine epilogue.
// Per (bc, h, lT): M=64 l, N=64 p, K=128 n. Warp tile 32x16.
// ---------------------------------------------------------------------------
__global__ __launch_bounds__(256) void yoff_kernel(const float* __restrict__ Dv) {
    int bc = blockIdx.x, h = blockIdx.y, lT = blockIdx.z;
    int b = bc / Nc, c = bc % Nc;
    int tid = threadIdx.x;
    int lane = tid & 31;
    int warp = tid >> 5;
    int wm = warp >> 2;
    int wn = warp & 3;
    int rowbase = b * Ll + c * Ck + lT * 64;

    __shared__ __align__(16) __half Cs[64][136];
    __shared__ __align__(16) __half Ps[64][136];
    __shared__ float lAc[64];

    const float* acumC = g_acum + ((size_t)bc * Hh + h) * Ck;
    if (tid < 64) lAc[tid] = acumC[lT * 64 + tid];
    const float* pprev = g_prev + ((size_t)bc * Hh + h) * Pp * Nn;

#pragma unroll
    for (int i = 0; i < 8; i++) {
        int q = tid + (i << 8);
        int row = q >> 5;
        int c4 = (q & 31) * 4;
        float4 vc = ldg4(g_conv + (size_t)(rowbase + row) * ConvD + Inter + Nn + c4);
        *(half2*)&Cs[row][c4]     = __floats2half2_rn(vc.x, vc.y);
        *(half2*)&Cs[row][c4 + 2] = __floats2half2_rn(vc.z, vc.w);
        float4 vp = ldg4(pprev + (size_t)row * Nn + c4);
        *(half2*)&Ps[row][c4]     = __floats2half2_rn(vp.x, vp.y);
        *(half2*)&Ps[row][c4 + 2] = __floats2half2_rn(vp.z, vp.w);
    }
    __syncthreads();

    const unsigned cbase = su32(Cs);
    const unsigned pbase = su32(Ps);
    float acc[2][2][4];
#pragma unroll
    for (int i = 0; i < 2; i++)
#pragma unroll
        for (int j = 0; j < 2; j++)
#pragma unroll
            for (int k = 0; k < 4; k++) acc[i][j][k] = 0.f;

    const int rA = lane & 15;
    const int cB = (lane >> 4) << 4;
#pragma unroll
    for (int ks = 0; ks < 8; ks++) {
        unsigned colb = (unsigned)(ks * 32 + cB);
        unsigned a[2][4], bb[2][2];
#pragma unroll
        for (int mf = 0; mf < 2; mf++) {
            unsigned ra = cbase + (wm * 32 + mf * 16 + rA) * 272 + colb;
            ldsm4(a[mf][0], a[mf][1], a[mf][2], a[mf][3], ra);
        }
        {
            unsigned rb = pbase + (wn * 16 + rA) * 272 + colb;
            unsigned t0, t1, t2, t3;
            ldsm4(t0, t1, t2, t3, rb);
            bb[0][0] = t0; bb[0][1] = t2;
            bb[1][0] = t1; bb[1][1] = t3;
        }
#pragma unroll
        for (int mf = 0; mf < 2; mf++)
#pragma unroll
            for (int nf = 0; nf < 2; nf++)
                mma16816(acc[mf][nf], a[mf], bb[nf]);
    }

    float Dh = Dv[h];
    int g4 = lane >> 2, t4 = lane & 3;
#pragma unroll
    for (int mf = 0; mf < 2; mf++) {
#pragma unroll
        for (int g = 0; g < 2; g++) {
            int ll = wm * 32 + mf * 16 + g4 + 8 * g;
            int l = rowbase + ll;
            float sd = expf(lAc[ll]);
#pragma unroll
            for (int nf = 0; nf < 2; nf++) {
                int p = wn * 16 + nf * 8 + t4 * 2;
                const float* ph = g_conv + (size_t)l * ConvD + h * Pp + p;
                float* py = g_y + (size_t)l * Inter + h * Pp + p;
                py[0] = py[0] + acc[mf][nf][2 * g + 0] * sd + Dh * ph[0];
                py[1] = py[1] + acc[mf][nf][2 * g + 1] * sd + Dh * ph[1];
            }
        }
    }
}

// ---------------------------------------------------------------------------
// Gated RMSNorm; writes fp16-rounded y for the 1-pass out-proj
// ---------------------------------------------------------------------------
__global__ __launch_bounds__(256) void norm_kernel(const float* __restrict__ norm_w) {
    int row = blockIdx.x;
    int tid = threadIdx.x;
    const float* pg = g_proj + (size_t)row * ProjD;
    const float* py = g_y + (size_t)row * Inter;
    float f[8];
    float ss = 0.f;
#pragma unroll
    for (int u = 0; u < 8; u++) {
        int i = tid + u * 256;
        float g = pg[i];
        float v = py[i] * siluf(g);
        f[u] = v;
        ss += v * v;
    }
    __shared__ float red[8];
    int lane = tid & 31, wid = tid >> 5;
#pragma unroll
    for (int o = 16; o > 0; o >>= 1) ss += __shfl_xor_sync(0xffffffffu, ss, o);
    if (lane == 0) red[wid] = ss;
    __syncthreads();
    if (tid == 0) {
        float t = 0.f;
#pragma unroll
        for (int i = 0; i < 8; i++) t += red[i];
        red[0] = t;
    }
    __syncthreads();
    float rs = rsqrtf(red[0] / (float)Inter + 1e-6f);
#pragma unroll
    for (int u = 0; u < 8; u++) {
        int i = tid + u * 256;
        float v = f[u] * rs * norm_w[i];
        g_Ah[(size_t)row * Inter + i] = __float2half(v);
    }
}

// ---------------------------------------------------------------------------
// Launch
// ---------------------------------------------------------------------------
extern "C" void kernel_launch(void* const* d_in, const int* in_sizes, int n_in,
                              void* d_out, int out_size) {
    const float* x         = (const float*)d_in[0];
    const float* in_proj_w = (const float*)d_in[1];
    const float* conv_w    = (const float*)d_in[2];
    const float* conv_b    = (const float*)d_in[3];
    const float* dt_bias   = (const float*)d_in[4];
    const float* A_log     = (const float*)d_in[5];
    const float* Dv        = (const float*)d_in[6];
    const float* norm_w    = (const float*)d_in[7];
    const float* out_proj_w= (const float*)d_in[8];
    float* out = (float*)d_out;

    cudaFuncSetAttribute(gemm_in_kernel, cudaFuncAttributeMaxDynamicSharedMemorySize, GEMM_SMEM);
    cudaFuncSetAttribute(gemm_out_kernel, cudaFuncAttributeMaxDynamicSharedMemorySize, GEMM_SMEM);

    // 1) round x and in_proj_w to fp16
    {
        int n = BL * Dm;
        round_x_kernel<<<(n + 255) / 256, 256>>>(x, n);
        n = ProjD * Dm;
        round_w_kernel<<<(n + 255) / 256, 256>>>(in_proj_w, n);
    }
    // 2) in-projection GEMM (1-pass fp16)
    {
        dim3 grid((ProjD + 127) / 128, BL / 128);
        gemm_in_kernel<<<grid, 256, GEMM_SMEM>>>();
    }
    // 3) conv + SiLU
    {
        dim3 grid(ConvD / 256, Ll / 32, Bb);
        conv_silu_kernel<<<grid, 256>>>(conv_w, conv_b);
    }
    // 4) cumsum of dt*A (fused softplus)
    acum_kernel<<<Bb * Nc * Hh, Ck>>>(A_log, dt_bias);
    // 5) Gm = C B^T (fp16 mma)
    {
        dim3 grid(Bb * Nc, Ck / 64, Ck / 64);
        gm_kernel<<<grid, 256>>>();
    }
    // 6) Y_diag
    {
        dim3 grid(Bb * Nc, Hh, Ck / 64);
        ydiag_kernel<<<grid, 256>>>();
    }
    // 7) states
    {
        dim3 grid(Bb * Nc, Hh);
        states_kernel<<<grid, 256>>>();
    }
    // 8) inter-chunk recurrence
    {
        int total = Bb * Hh * Pp * Nn;
        prev_kernel<<<(total + 255) / 256, 256>>>();
    }
    // 9) Y_off + combine (fp16 mma)
    {
        dim3 grid(Bb * Nc, Hh, Ck / 64);
        yoff_kernel<<<grid, 256>>>(Dv);
    }
    // 10) gated RMSNorm (writes fp16 y)
    norm_kernel<<<BL, 256>>>(norm_w);
    // 11) round out_proj_w to fp16
    {
        int n = Dm * Inter;
        round_w_kernel<<<(n + 255) / 256, 256>>>(out_proj_w, n);
    }
    // 12) out-projection GEMM (1-pass fp16)
    {
        dim3 grid(Dm / 128, BL / 128);
        gemm_out_kernel<<<grid, 256, GEMM_SMEM>>>(out);
    }
    (void)in_sizes; (void)n_in; (void)out_size;
}

// round 13
// speedup vs baseline: 1.4707x; 1.4707x over previous
#include <cuda_runtime.h>
#include <cuda_fp16.h>
#include <math.h>
#include <stdint.h>

// ---------------------------------------------------------------------------
// Problem constants (fixed shapes)
// ---------------------------------------------------------------------------
#define Bb     2
#define Ll     2048
#define Dm     1024
#define Hh     32
#define Pp     64
#define Nn     128
#define KCONV  4
#define Ck     256
#define Nc     8          // Ll / Ck
#define Inter  2048
#define ConvD  2304
#define ProjD  4384
#define BL     (Bb * Ll)  // 4096

// ---------------------------------------------------------------------------
// Scratch (device globals; no dynamic allocation allowed)
// ---------------------------------------------------------------------------
__device__ float g_proj[(size_t)BL * ProjD];
__device__ float g_conv[(size_t)BL * ConvD];
__device__ float g_dtv[(size_t)BL * Hh];
__device__ float g_acum[(size_t)Bb * Nc * Hh * Ck];
__device__ float g_gm[(size_t)Bb * Nc * Ck * Ck];
__device__ float g_y[(size_t)BL * Inter];
__device__ float g_states[(size_t)Bb * Nc * Hh * Pp * Nn];
__device__ float g_prev[(size_t)Bb * Nc * Hh * Pp * Nn];

// fp16 buffers
__device__ __half g_Ah[(size_t)BL * Inter];
__device__ __half g_Bh[(size_t)ProjD * Dm];

__device__ __forceinline__ float siluf(float x) { return x / (1.f + expf(-x)); }

__device__ __forceinline__ float4 ldg4(const float* p) {
    return *reinterpret_cast<const float4*>(p);
}

// ---------------------------------------------------------------------------
// PTX helpers
// ---------------------------------------------------------------------------
__device__ __forceinline__ unsigned su32(const void* p) {
    return (unsigned)__cvta_generic_to_shared(p);
}

__device__ __forceinline__ void cp16(unsigned dst, const void* src, bool ok) {
    int sz = ok ? 16 : 0;
    asm volatile("cp.async.cg.shared.global [%0], [%1], 16, %2;\n"
                 :: "r"(dst), "l"(src), "r"(sz));
}

__device__ __forceinline__ void ldsm4(unsigned& r0, unsigned& r1, unsigned& r2, unsigned& r3,
                                      unsigned addr) {
    asm volatile("ldmatrix.sync.aligned.m8n8.x4.shared.b16 {%0,%1,%2,%3}, [%4];"
                 : "=r"(r0), "=r"(r1), "=r"(r2), "=r"(r3) : "r"(addr));
}

__device__ __forceinline__ void mma16816(float* c, const unsigned* a, const unsigned* b) {
    asm volatile(
        "mma.sync.aligned.m16n8k16.row.col.f32.f16.f16.f32 "
        "{%0,%1,%2,%3}, {%4,%5,%6,%7}, {%8,%9}, {%0,%1,%2,%3};"
        : "+f"(c[0]), "+f"(c[1]), "+f"(c[2]), "+f"(c[3])
        : "r"(a[0]), "r"(a[1]), "r"(a[2]), "r"(a[3]), "r"(b[0]), "r"(b[1]));
}

// ---------------------------------------------------------------------------
// Tensor-core fp16 GEMM, 1-pass: C = Ah*Bh, fp32 accum. (proven R10/R11)
// ---------------------------------------------------------------------------
#define GEMM_SMEM (2 * 36864)

struct Frags {
    unsigned ah[4][4];
    unsigned bh[4][2];
};

__device__ __forceinline__ void load_frags(Frags& F, unsigned stg, int ks,
                                           int wm, int wn, int lane) {
    const int rA = lane & 15;
    const int cB = ((lane >> 4) << 4);
    const unsigned colb = (unsigned)(ks * 32 + cB);
#pragma unroll
    for (int mf = 0; mf < 4; mf++) {
        unsigned ra = stg + (wm * 64 + mf * 16 + rA) * 144 + colb;
        ldsm4(F.ah[mf][0], F.ah[mf][1], F.ah[mf][2], F.ah[mf][3], ra);
    }
#pragma unroll
    for (int nf2 = 0; nf2 < 2; nf2++) {
        unsigned rb = stg + 18432 + (wn * 32 + nf2 * 16 + rA) * 144 + colb;
        unsigned t0, t1, t2, t3;
        ldsm4(t0, t1, t2, t3, rb);
        F.bh[nf2 * 2][0] = t0; F.bh[nf2 * 2][1] = t2;
        F.bh[nf2 * 2 + 1][0] = t1; F.bh[nf2 * 2 + 1][1] = t3;
    }
}

__device__ __forceinline__ void gemm_core(const __half* __restrict__ Ah,
                                          const __half* __restrict__ Bh,
                                          float* __restrict__ C,
                                          int M, int N, int K) {
    extern __shared__ char dyn[];
    const unsigned sbase = su32(dyn);
    const int tid = threadIdx.x;
    const int lane = tid & 31;
    const int warp = tid >> 5;
    const int wm = warp >> 2;
    const int wn = warp & 3;
    const int m0 = blockIdx.y * 128;
    const int n0 = blockIdx.x * 128;
    const int KB = K >> 6;

    float acc[4][4][4];
#pragma unroll
    for (int a = 0; a < 4; a++)
#pragma unroll
        for (int b = 0; b < 4; b++)
#pragma unroll
            for (int c = 0; c < 4; c++) acc[a][b][c] = 0.f;

    auto issue = [&](int kc, int st) {
        unsigned stg = sbase + st * 36864;
#pragma unroll
        for (int i = 0; i < 8; i++) {
            int q = tid + (i << 8);
            int mat = q >> 10;
            int r = (q >> 3) & 127;
            int c16 = q & 7;
            const __half* base = mat ? Bh : Ah;
            int gr = (mat ? n0 : m0) + r;
            bool ok = gr < (mat ? N : M);
            if (!ok) gr = (mat ? N : M) - 1;
            const void* src = base + (size_t)gr * K + (kc << 6) + (c16 << 3);
            unsigned dst = stg + mat * 18432 + r * 144 + (c16 << 4);
            cp16(dst, src, ok);
        }
        asm volatile("cp.async.commit_group;\n");
    };

    issue(0, 0);
    if (KB > 1) issue(1, 1);

    Frags F[2];

    for (int kb = 0; kb < KB; kb++) {
        int st = kb & 1;
        if (kb + 1 < KB) asm volatile("cp.async.wait_group 1;\n");
        else             asm volatile("cp.async.wait_group 0;\n");
        __syncthreads();
        unsigned stg = sbase + st * 36864;

        load_frags(F[0], stg, 0, wm, wn, lane);
#pragma unroll
        for (int ks = 0; ks < 4; ks++) {
            if (ks < 3) load_frags(F[(ks + 1) & 1], stg, ks + 1, wm, wn, lane);
            Frags& f = F[ks & 1];
#pragma unroll
            for (int mf = 0; mf < 4; mf++)
#pragma unroll
                for (int nf = 0; nf < 4; nf++)
                    mma16816(acc[mf][nf], f.ah[mf], f.bh[nf]);
        }
        __syncthreads();
        if (kb + 2 < KB) issue(kb + 2, st);
    }

    int g4 = lane >> 2, t4 = lane & 3;
#pragma unroll
    for (int mf = 0; mf < 4; mf++) {
        int r0 = m0 + wm * 64 + mf * 16 + g4;
#pragma unroll
        for (int nf = 0; nf < 4; nf++) {
            int cg = n0 + wn * 32 + nf * 8 + t4 * 2;
            if (cg < N) {
                float* p0 = C + (size_t)r0 * N + cg;
                p0[0] = acc[mf][nf][0];
                p0[1] = acc[mf][nf][1];
                float* p1 = p0 + (size_t)8 * N;
                p1[0] = acc[mf][nf][2];
                p1[1] = acc[mf][nf][3];
            }
        }
    }
}

__global__ __launch_bounds__(256) void gemm_in_kernel() {
    gemm_core(g_Ah, g_Bh, g_proj, BL, ProjD, Dm);
}

__global__ __launch_bounds__(256) void gemm_out_kernel(float* __restrict__ out) {
    gemm_core(g_Ah, g_Bh, out, BL, Dm, Inter);
}

// ---------------------------------------------------------------------------
// fp16 conversions
// ---------------------------------------------------------------------------
__global__ void round_x_kernel(const float* __restrict__ in, int n) {
    int i = blockIdx.x * blockDim.x + threadIdx.x;
    if (i >= n) return;
    g_Ah[i] = __float2half(in[i]);
}

__global__ void round_w_kernel(const float* __restrict__ in, int n) {
    int i = blockIdx.x * blockDim.x + threadIdx.x;
    if (i >= n) return;
    g_Bh[i] = __float2half(in[i]);
}

// ---------------------------------------------------------------------------
// Depthwise causal conv1d + SiLU (sliding window, 32 positions/thread)
// ---------------------------------------------------------------------------
__global__ __launch_bounds__(256) void conv_silu_kernel(const float* __restrict__ cw,
                                                        const float* __restrict__ cb) {
    int ch = blockIdx.x * 256 + threadIdx.x;
    int l0 = blockIdx.y * 32;
    int b  = blockIdx.z;
    const float* col = g_proj + (size_t)b * Ll * ProjD + Inter + ch;
    float w0 = cw[ch * KCONV + 0];
    float w1 = cw[ch * KCONV + 1];
    float w2 = cw[ch * KCONV + 2];
    float w3 = cw[ch * KCONV + 3];
    float bias = cb[ch];
    float xm3 = (l0 >= 3) ? col[(size_t)(l0 - 3) * ProjD] : 0.f;
    float xm2 = (l0 >= 2) ? col[(size_t)(l0 - 2) * ProjD] : 0.f;
    float xm1 = (l0 >= 1) ? col[(size_t)(l0 - 1) * ProjD] : 0.f;
    float* outp = g_conv + (size_t)(b * Ll + l0) * ConvD + ch;
#pragma unroll 4
    for (int i = 0; i < 32; i++) {
        float x0 = col[(size_t)(l0 + i) * ProjD];
        float acc = bias + w0 * xm3 + w1 * xm2 + w2 * xm1 + w3 * x0;
        outp[(size_t)i * ConvD] = siluf(acc);
        xm3 = xm2; xm2 = xm1; xm1 = x0;
    }
}

// ---------------------------------------------------------------------------
// Per-chunk inclusive cumsum of dt * A with fused softplus
// ---------------------------------------------------------------------------
__global__ void acum_kernel(const float* __restrict__ A_log,
                            const float* __restrict__ dt_bias) {
    int blk = blockIdx.x;
    int h = blk % Hh;
    int bc = blk / Hh;
    int b = bc / Nc, c = bc % Nc;
    int t = threadIdx.x;
    float A = -expf(A_log[h]);
    int bl = b * Ll + c * Ck + t;
    float raw = g_proj[(size_t)bl * ProjD + Inter + ConvD + h] + dt_bias[h];
    float dt = (raw > 20.f) ? raw : log1pf(expf(raw));
    g_dtv[(size_t)bl * Hh + h] = dt;
    float v = dt * A;
    __shared__ float s[Ck];
    s[t] = v;
    __syncthreads();
    for (int off = 1; off < Ck; off <<= 1) {
        float x = (t >= off) ? s[t - off] : 0.f;
        __syncthreads();
        s[t] += x;
        __syncthreads();
    }
    g_acum[(size_t)blk * Ck + t] = s[t];
}

// ---------------------------------------------------------------------------
// Gm[s,z] = sum_n C[s,n] * B[z,n] per (b,c), lower triangle (fp32, R11)
// ---------------------------------------------------------------------------
__global__ __launch_bounds__(256) void gm_kernel() {
    int bc = blockIdx.x;
    int sT = blockIdx.y, zT = blockIdx.z;
    if (zT > sT) return;
    int b = bc / Nc, c = bc % Nc;
    int rowbase = b * Ll + c * Ck;
    __shared__ __align__(16) float Cs[16][68];
    __shared__ __align__(16) float Bs[16][68];
    int tid = threadIdx.x;
    int ty = tid >> 4, tx = tid & 15;
    float acc[4][4];
#pragma unroll
    for (int i = 0; i < 4; i++)
#pragma unroll
        for (int j = 0; j < 4; j++) acc[i][j] = 0.f;

    int lrow = tid >> 2;
    int lcol = (tid & 3) * 4;

    for (int n0 = 0; n0 < Nn; n0 += 16) {
        float4 vc = ldg4(g_conv + (size_t)(rowbase + sT * 64 + lrow) * ConvD + Inter + Nn + n0 + lcol);
        float4 vb = ldg4(g_conv + (size_t)(rowbase + zT * 64 + lrow) * ConvD + Inter + n0 + lcol);
        Cs[lcol + 0][lrow] = vc.x; Cs[lcol + 1][lrow] = vc.y;
        Cs[lcol + 2][lrow] = vc.z; Cs[lcol + 3][lrow] = vc.w;
        Bs[lcol + 0][lrow] = vb.x; Bs[lcol + 1][lrow] = vb.y;
        Bs[lcol + 2][lrow] = vb.z; Bs[lcol + 3][lrow] = vb.w;
        __syncthreads();
#pragma unroll
        for (int kk = 0; kk < 16; kk++) {
            float4 rc = *(const float4*)&Cs[kk][ty * 4];
            float4 rb = *(const float4*)&Bs[kk][tx * 4];
            float rcv[4] = {rc.x, rc.y, rc.z, rc.w};
            float rbv[4] = {rb.x, rb.y, rb.z, rb.w};
#pragma unroll
            for (int i = 0; i < 4; i++)
#pragma unroll
                for (int j = 0; j < 4; j++) acc[i][j] += rcv[i] * rbv[j];
        }
        __syncthreads();
    }
#pragma unroll
    for (int i = 0; i < 4; i++) {
        int sg = sT * 64 + ty * 4 + i;
        float* pg = g_gm + ((size_t)bc * Ck + sg) * Ck + zT * 64 + tx * 4;
        *reinterpret_cast<float4*>(pg) = make_float4(acc[i][0], acc[i][1], acc[i][2], acc[i][3]);
    }
}

// ---------------------------------------------------------------------------
// states — fp32 (R11)
// ---------------------------------------------------------------------------
__global__ __launch_bounds__(256) void states_kernel() {
    int bc = blockIdx.x, h = blockIdx.y;
    int b = bc / Nc, c = bc % Nc;
    int tid = threadIdx.x;
    int ty = tid >> 4, tx = tid & 15;
    __shared__ __align__(16) float Hd[32][68];
    __shared__ __align__(16) float Bsm[32][132];
    const float* acumC = g_acum + ((size_t)bc * Hh + h) * Ck;
    float aLast = acumC[Ck - 1];
    int rowbase = b * Ll + c * Ck;
    float acc[4][8];
#pragma unroll
    for (int i = 0; i < 4; i++)
#pragma unroll
        for (int j = 0; j < 8; j++) acc[i][j] = 0.f;

    for (int l0 = 0; l0 < Ck; l0 += 32) {
        {
            int ll = tid >> 3;
            int p0 = (tid & 7) * 8;
            int l = rowbase + l0 + ll;
            float w = g_dtv[(size_t)l * Hh + h] * expf(aLast - acumC[l0 + ll]);
            const float* ph = g_conv + (size_t)l * ConvD + h * Pp + p0;
#pragma unroll
            for (int u = 0; u < 2; u++) {
                float4 v = ldg4(ph + u * 4);
                *reinterpret_cast<float4*>(&Hd[ll][p0 + u * 4]) =
                    make_float4(v.x * w, v.y * w, v.z * w, v.w * w);
            }
        }
        {
            int ll = tid >> 3;
            int n0v = (tid & 7) * 16;
            const float* pb = g_conv + (size_t)(rowbase + l0 + ll) * ConvD + Inter + n0v;
#pragma unroll
            for (int u = 0; u < 4; u++)
                *reinterpret_cast<float4*>(&Bsm[ll][n0v + u * 4]) = ldg4(pb + u * 4);
        }
        __syncthreads();
#pragma unroll 4
        for (int ll = 0; ll < 32; ll++) {
            float4 rh4 = *(const float4*)&Hd[ll][ty * 4];
            float4 rb0 = *(const float4*)&Bsm[ll][tx * 8];
            float4 rb1 = *(const float4*)&Bsm[ll][tx * 8 + 4];
            float rh[4] = {rh4.x, rh4.y, rh4.z, rh4.w};
            float rb[8] = {rb0.x, rb0.y, rb0.z, rb0.w, rb1.x, rb1.y, rb1.z, rb1.w};
#pragma unroll
            for (int i = 0; i < 4; i++)
#pragma unroll
                for (int j = 0; j < 8; j++) acc[i][j] += rh[i] * rb[j];
        }
        __syncthreads();
    }
    float* ps = g_states + ((size_t)bc * Hh + h) * Pp * Nn;
#pragma unroll
    for (int i = 0; i < 4; i++) {
        float* p = ps + (ty * 4 + i) * Nn + tx * 8;
        *reinterpret_cast<float4*>(p) = make_float4(acc[i][0], acc[i][1], acc[i][2], acc[i][3]);
        *reinterpret_cast<float4*>(p + 4) = make_float4(acc[i][4], acc[i][5], acc[i][6], acc[i][7]);
    }
}

// ---------------------------------------------------------------------------
// Inter-chunk recurrence
// ---------------------------------------------------------------------------
__global__ void prev_kernel() {
    int idx = blockIdx.x * blockDim.x + threadIdx.x;
    if (idx >= Bb * Hh * Pp * Nn) return;
    int n = idx % Nn;
    int p = (idx / Nn) % Pp;
    int h = (idx / (Nn * Pp)) % Hh;
    int b = idx / (Nn * Pp * Hh);
    float r = 0.f;
    for (int c = 0; c < Nc; c++) {
        size_t off = (((size_t)(b * Nc + c) * Hh + h) * Pp + p) * Nn + n;
        g_prev[off] = r;
        float zl = g_acum[((size_t)(b * Nc + c) * Hh + h) * Ck + (Ck - 1)];
        r = g_states[off] + expf(zl) * r;
    }
}

// ---------------------------------------------------------------------------
// FUSED Y_diag + Y_off + D residual. Block = (bc, h, sT). Writes g_y once.
// Y[l,p] = Ydiag + Yoff*exp(Acum[l]) + D[h]*hs[l,p]
// ---------------------------------------------------------------------------
__global__ __launch_bounds__(256) void ydiag_yoff_kernel(const float* __restrict__ Dv) {
    int bc = blockIdx.x;
    int h = blockIdx.y;
    int sT = blockIdx.z;
    int b = bc / Nc, c = bc % Nc;
    int tid = threadIdx.x;
    int ty = tid >> 4, tx = tid & 15;

    __shared__ float Ms[64][65];
    __shared__ __align__(16) float Hs[64][68];
    __shared__ __align__(16) float Cs[16][68];
    __shared__ __align__(16) float Ps[16][68];
    __shared__ float sAc[64], zAc[64], ezs[64];

    const float* acumC = g_acum + ((size_t)bc * Hh + h) * Ck;
    if (tid < 64) sAc[tid] = acumC[sT * 64 + tid];
    int rowbase = b * Ll + c * Ck;
    int lbase = rowbase + sT * 64;

    float accd[4][4];
#pragma unroll
    for (int i = 0; i < 4; i++)
#pragma unroll
        for (int j = 0; j < 4; j++) accd[i][j] = 0.f;

    // ---- Y_diag over causal z-tiles ----
    for (int zT = 0; zT <= sT; zT++) {
        float M = acumC[zT * 64 + 63];
        if (tid < 64) {
            float az = acumC[zT * 64 + tid];
            zAc[tid] = az;
            ezs[tid] = expf(M - az);
        }
        {
            int zz = tid >> 2;
            int p0 = (tid & 3) * 16;
            int l = rowbase + zT * 64 + zz;
            float d = g_dtv[(size_t)l * Hh + h];
            const float* ph = g_conv + (size_t)l * ConvD + h * Pp + p0;
#pragma unroll
            for (int u = 0; u < 4; u++) {
                float4 v = ldg4(ph + u * 4);
                *reinterpret_cast<float4*>(&Hs[zz][p0 + u * 4]) =
                    make_float4(v.x * d, v.y * d, v.z * d, v.w * d);
            }
        }
        __syncthreads();
        {
            int zz4 = (tid & 15) * 4;
            int ss4 = (tid >> 4) * 4;
            if (zT < sT) {
#pragma unroll
                for (int a = 0; a < 4; a++) {
                    int ss = ss4 + a;
                    int sg = sT * 64 + ss;
                    float es = expf(sAc[ss] - M);
                    float4 g = ldg4(g_gm + ((size_t)bc * Ck + sg) * Ck + zT * 64 + zz4);
                    Ms[zz4 + 0][ss] = g.x * ezs[zz4 + 0] * es;
                    Ms[zz4 + 1][ss] = g.y * ezs[zz4 + 1] * es;
                    Ms[zz4 + 2][ss] = g.z * ezs[zz4 + 2] * es;
                    Ms[zz4 + 3][ss] = g.w * ezs[zz4 + 3] * es;
                }
            } else {
#pragma unroll
                for (int a = 0; a < 4; a++) {
                    int ss = ss4 + a;
                    int sg = sT * 64 + ss;
                    float as = sAc[ss];
                    float4 g = ldg4(g_gm + ((size_t)bc * Ck + sg) * Ck + zT * 64 + zz4);
                    float gv[4] = {g.x, g.y, g.z, g.w};
#pragma unroll
                    for (int q = 0; q < 4; q++) {
                        int zz = zz4 + q;
                        float m = 0.f;
                        if ((zT * 64 + zz) <= sg)
                            m = gv[q] * expf(as - zAc[zz]);
                        Ms[zz][ss] = m;
                    }
                }
            }
        }
        __syncthreads();
#pragma unroll 4
        for (int zz = 0; zz < 64; zz++) {
            float rm[4];
#pragma unroll
            for (int i = 0; i < 4; i++) rm[i] = Ms[zz][ty * 4 + i];
            float4 rh = *(const float4*)&Hs[zz][tx * 4];
            float rhv[4] = {rh.x, rh.y, rh.z, rh.w};
#pragma unroll
            for (int i = 0; i < 4; i++)
#pragma unroll
                for (int j = 0; j < 4; j++) accd[i][j] += rm[i] * rhv[j];
        }
        __syncthreads();
    }

    // ---- Y_off: sum_n C[l,n] * prev[p,n] ----
    float acco[4][4];
#pragma unroll
    for (int i = 0; i < 4; i++)
#pragma unroll
        for (int j = 0; j < 4; j++) acco[i][j] = 0.f;

    const float* pprev = g_prev + ((size_t)bc * Hh + h) * Pp * Nn;
    int lrow = tid >> 2;
    int lcol = (tid & 3) * 4;
    for (int n0 = 0; n0 < Nn; n0 += 16) {
        float4 vc = ldg4(g_conv + (size_t)(lbase + lrow) * ConvD + Inter + Nn + n0 + lcol);
        Cs[lcol + 0][lrow] = vc.x; Cs[lcol + 1][lrow] = vc.y;
        Cs[lcol + 2][lrow] = vc.z; Cs[lcol + 3][lrow] = vc.w;
        float4 vp = ldg4(pprev + (size_t)lrow * Nn + n0 + lcol);
        Ps[lcol + 0][lrow] = vp.x; Ps[lcol + 1][lrow] = vp.y;
        Ps[lcol + 2][lrow] = vp.z; Ps[lcol + 3][lrow] = vp.w;
        __syncthreads();
#pragma unroll
        for (int kk = 0; kk < 16; kk++) {
            float4 rc = *(const float4*)&Cs[kk][ty * 4];
            float4 rp = *(const float4*)&Ps[kk][tx * 4];
            float rcv[4] = {rc.x, rc.y, rc.z, rc.w};
            float rpv[4] = {rp.x, rp.y, rp.z, rp.w};
#pragma unroll
            for (int i = 0; i < 4; i++)
#pragma unroll
                for (int j = 0; j < 4; j++) acco[i][j] += rcv[i] * rpv[j];
        }
        __syncthreads();
    }

    // ---- combine + single write ----
    float Dh = Dv[h];
#pragma unroll
    for (int i = 0; i < 4; i++) {
        int ll = ty * 4 + i;
        int l = lbase + ll;
        float sd = expf(sAc[ll]);
        float4 hv = ldg4(g_conv + (size_t)l * ConvD + h * Pp + tx * 4);
        float* py = g_y + (size_t)l * Inter + h * Pp + tx * 4;
        float4 yv;
        yv.x = accd[i][0] + acco[i][0] * sd + Dh * hv.x;
        yv.y = accd[i][1] + acco[i][1] * sd + Dh * hv.y;
        yv.z = accd[i][2] + acco[i][2] * sd + Dh * hv.z;
        yv.w = accd[i][3] + acco[i][3] * sd + Dh * hv.w;
        *reinterpret_cast<float4*>(py) = yv;
    }
}

// ---------------------------------------------------------------------------
// Gated RMSNorm; writes fp16-rounded y for the 1-pass out-proj
// ---------------------------------------------------------------------------
__global__ __launch_bounds__(256) void norm_kernel(const float* __restrict__ norm_w) {
    int row = blockIdx.x;
    int tid = threadIdx.x;
    const float* pg = g_proj + (size_t)row * ProjD;
    const float* py = g_y + (size_t)row * Inter;
    float f[8];
    float ss = 0.f;
#pragma unroll
    for (int u = 0; u < 8; u++) {
        int i = tid + u * 256;
        float g = pg[i];
        float v = py[i] * siluf(g);
        f[u] = v;
        ss += v * v;
    }
    __shared__ float red[8];
    int lane = tid & 31, wid = tid >> 5;
#pragma unroll
    for (int o = 16; o > 0; o >>= 1) ss += __shfl_xor_sync(0xffffffffu, ss, o);
    if (lane == 0) red[wid] = ss;
    __syncthreads();
    if (tid == 0) {
        float t = 0.f;
#pragma unroll
        for (int i = 0; i < 8; i++) t += red[i];
        red[0] = t;
    }
    __syncthreads();
    float rs = rsqrtf(red[0] / (float)Inter + 1e-6f);
#pragma unroll
    for (int u = 0; u < 8; u++) {
        int i = tid + u * 256;
        float v = f[u] * rs * norm_w[i];
        g_Ah[(size_t)row * Inter + i] = __float2half(v);
    }
}

// ---------------------------------------------------------------------------
// Launch
// ---------------------------------------------------------------------------
extern "C" void kernel_launch(void* const* d_in, const int* in_sizes, int n_in,
                              void* d_out, int out_size) {
    const float* x         = (const float*)d_in[0];
    const float* in_proj_w = (const float*)d_in[1];
    const float* conv_w    = (const float*)d_in[2];
    const float* conv_b    = (const float*)d_in[3];
    const float* dt_bias   = (const float*)d_in[4];
    const float* A_log     = (const float*)d_in[5];
    const float* Dv        = (const float*)d_in[6];
    const float* norm_w    = (const float*)d_in[7];
    const float* out_proj_w= (const float*)d_in[8];
    float* out = (float*)d_out;

    cudaFuncSetAttribute(gemm_in_kernel, cudaFuncAttributeMaxDynamicSharedMemorySize, GEMM_SMEM);
    cudaFuncSetAttribute(gemm_out_kernel, cudaFuncAttributeMaxDynamicSharedMemorySize, GEMM_SMEM);

    // 1) round x and in_proj_w to fp16
    {
        int n = BL * Dm;
        round_x_kernel<<<(n + 255) / 256, 256>>>(x, n);
        n = ProjD * Dm;
        round_w_kernel<<<(n + 255) / 256, 256>>>(in_proj_w, n);
    }
    // 2) in-projection GEMM (1-pass fp16)
    {
        dim3 grid((ProjD + 127) / 128, BL / 128);
        gemm_in_kernel<<<grid, 256, GEMM_SMEM>>>();
    }
    // 3) conv + SiLU
    {
        dim3 grid(ConvD / 256, Ll / 32, Bb);
        conv_silu_kernel<<<grid, 256>>>(conv_w, conv_b);
    }
    // 4) cumsum of dt*A (fused softplus)
    acum_kernel<<<Bb * Nc * Hh, Ck>>>(A_log, dt_bias);
    // 5) Gm = C B^T
    {
        dim3 grid(Bb * Nc, Ck / 64, Ck / 64);
        gm_kernel<<<grid, 256>>>();
    }
    // 6) states
    {
        dim3 grid(Bb * Nc, Hh);
        states_kernel<<<grid, 256>>>();
    }
    // 7) inter-chunk recurrence
    {
        int total = Bb * Hh * Pp * Nn;
        prev_kernel<<<(total + 255) / 256, 256>>>();
    }
    // 8) fused Y_diag + Y_off + D residual (single g_y write)
    {
        dim3 grid(Bb * Nc, Hh, Ck / 64);
        ydiag_yoff_kernel<<<grid, 256>>>(Dv);
    }
    // 9) gated RMSNorm (writes fp16 y)
    norm_kernel<<<BL, 256>>>(norm_w);
    // 10) round out_proj_w to fp16
    {
        int n = Dm * Inter;
        round_w_kernel<<<(n + 255) / 256, 256>>>(out_proj_w, n);
    }
    // 11) out-projection GEMM (1-pass fp16)
    {
        dim3 grid(Dm / 128, BL / 128);
        gemm_out_kernel<<<grid, 256, GEMM_SMEM>>>(out);
    }
    (void)in_sizes; (void)n_in; (void)out_size;
}

// round 14
// speedup vs baseline: 1.7571x; 1.1947x over previous
#include <cuda_runtime.h>
#include <cuda_fp16.h>
#include <math.h>
#include <stdint.h>

// ---------------------------------------------------------------------------
// Problem constants (fixed shapes)
// ---------------------------------------------------------------------------
#define Bb     2
#define Ll     2048
#define Dm     1024
#define Hh     32
#define Pp     64
#define Nn     128
#define KCONV  4
#define Ck     256
#define Nc     8          // Ll / Ck
#define Inter  2048
#define ConvD  2304
#define ProjD  4384
#define BL     (Bb * Ll)  // 4096

// ---------------------------------------------------------------------------
// Scratch (device globals; no dynamic allocation allowed)
// ---------------------------------------------------------------------------
__device__ float g_proj[(size_t)BL * ProjD];
__device__ float g_conv[(size_t)BL * ConvD];
__device__ float g_dtv[(size_t)BL * Hh];
__device__ float g_acum[(size_t)Bb * Nc * Hh * Ck];
__device__ float g_gm[(size_t)Bb * Nc * Ck * Ck];
__device__ float g_y[(size_t)BL * Inter];
__device__ float g_states[(size_t)Bb * Nc * Hh * Pp * Nn];
__device__ float g_prev[(size_t)Bb * Nc * Hh * Pp * Nn];

// fp16 buffers
__device__ __half g_Ah[(size_t)BL * Inter];
__device__ __half g_Bh[(size_t)ProjD * Dm];

__device__ __forceinline__ float siluf(float x) { return x / (1.f + expf(-x)); }

__device__ __forceinline__ float4 ldg4(const float* p) {
    return *reinterpret_cast<const float4*>(p);
}

// ---------------------------------------------------------------------------
// PTX helpers
// ---------------------------------------------------------------------------
__device__ __forceinline__ unsigned su32(const void* p) {
    return (unsigned)__cvta_generic_to_shared(p);
}

__device__ __forceinline__ void cp16(unsigned dst, const void* src, bool ok) {
    int sz = ok ? 16 : 0;
    asm volatile("cp.async.cg.shared.global [%0], [%1], 16, %2;\n"
                 :: "r"(dst), "l"(src), "r"(sz));
}

__device__ __forceinline__ void ldsm4(unsigned& r0, unsigned& r1, unsigned& r2, unsigned& r3,
                                      unsigned addr) {
    asm volatile("ldmatrix.sync.aligned.m8n8.x4.shared.b16 {%0,%1,%2,%3}, [%4];"
                 : "=r"(r0), "=r"(r1), "=r"(r2), "=r"(r3) : "r"(addr));
}

__device__ __forceinline__ void mma16816(float* c, const unsigned* a, const unsigned* b) {
    asm volatile(
        "mma.sync.aligned.m16n8k16.row.col.f32.f16.f16.f32 "
        "{%0,%1,%2,%3}, {%4,%5,%6,%7}, {%8,%9}, {%0,%1,%2,%3};"
        : "+f"(c[0]), "+f"(c[1]), "+f"(c[2]), "+f"(c[3])
        : "r"(a[0]), "r"(a[1]), "r"(a[2]), "r"(a[3]), "r"(b[0]), "r"(b[1]));
}

// ---------------------------------------------------------------------------
// Tensor-core fp16 GEMM, 1-pass: C = Ah*Bh, fp32 accum. (proven R10/R11)
// ---------------------------------------------------------------------------
#define GEMM_SMEM (2 * 36864)

struct Frags {
    unsigned ah[4][4];
    unsigned bh[4][2];
};

__device__ __forceinline__ void load_frags(Frags& F, unsigned stg, int ks,
                                           int wm, int wn, int lane) {
    const int rA = lane & 15;
    const int cB = ((lane >> 4) << 4);
    const unsigned colb = (unsigned)(ks * 32 + cB);
#pragma unroll
    for (int mf = 0; mf < 4; mf++) {
        unsigned ra = stg + (wm * 64 + mf * 16 + rA) * 144 + colb;
        ldsm4(F.ah[mf][0], F.ah[mf][1], F.ah[mf][2], F.ah[mf][3], ra);
    }
#pragma unroll
    for (int nf2 = 0; nf2 < 2; nf2++) {
        unsigned rb = stg + 18432 + (wn * 32 + nf2 * 16 + rA) * 144 + colb;
        unsigned t0, t1, t2, t3;
        ldsm4(t0, t1, t2, t3, rb);
        F.bh[nf2 * 2][0] = t0; F.bh[nf2 * 2][1] = t2;
        F.bh[nf2 * 2 + 1][0] = t1; F.bh[nf2 * 2 + 1][1] = t3;
    }
}

__device__ __forceinline__ void gemm_core(const __half* __restrict__ Ah,
                                          const __half* __restrict__ Bh,
                                          float* __restrict__ C,
                                          int M, int N, int K) {
    extern __shared__ char dyn[];
    const unsigned sbase = su32(dyn);
    const int tid = threadIdx.x;
    const int lane = tid & 31;
    const int warp = tid >> 5;
    const int wm = warp >> 2;
    const int wn = warp & 3;
    const int m0 = blockIdx.y * 128;
    const int n0 = blockIdx.x * 128;
    const int KB = K >> 6;

    float acc[4][4][4];
#pragma unroll
    for (int a = 0; a < 4; a++)
#pragma unroll
        for (int b = 0; b < 4; b++)
#pragma unroll
            for (int c = 0; c < 4; c++) acc[a][b][c] = 0.f;

    auto issue = [&](int kc, int st) {
        unsigned stg = sbase + st * 36864;
#pragma unroll
        for (int i = 0; i < 8; i++) {
            int q = tid + (i << 8);
            int mat = q >> 10;
            int r = (q >> 3) & 127;
            int c16 = q & 7;
            const __half* base = mat ? Bh : Ah;
            int gr = (mat ? n0 : m0) + r;
            bool ok = gr < (mat ? N : M);
            if (!ok) gr = (mat ? N : M) - 1;
            const void* src = base + (size_t)gr * K + (kc << 6) + (c16 << 3);
            unsigned dst = stg + mat * 18432 + r * 144 + (c16 << 4);
            cp16(dst, src, ok);
        }
        asm volatile("cp.async.commit_group;\n");
    };

    issue(0, 0);
    if (KB > 1) issue(1, 1);

    Frags F[2];

    for (int kb = 0; kb < KB; kb++) {
        int st = kb & 1;
        if (kb + 1 < KB) asm volatile("cp.async.wait_group 1;\n");
        else             asm volatile("cp.async.wait_group 0;\n");
        __syncthreads();
        unsigned stg = sbase + st * 36864;

        load_frags(F[0], stg, 0, wm, wn, lane);
#pragma unroll
        for (int ks = 0; ks < 4; ks++) {
            if (ks < 3) load_frags(F[(ks + 1) & 1], stg, ks + 1, wm, wn, lane);
            Frags& f = F[ks & 1];
#pragma unroll
            for (int mf = 0; mf < 4; mf++)
#pragma unroll
                for (int nf = 0; nf < 4; nf++)
                    mma16816(acc[mf][nf], f.ah[mf], f.bh[nf]);
        }
        __syncthreads();
        if (kb + 2 < KB) issue(kb + 2, st);
    }

    int g4 = lane >> 2, t4 = lane & 3;
#pragma unroll
    for (int mf = 0; mf < 4; mf++) {
        int r0 = m0 + wm * 64 + mf * 16 + g4;
#pragma unroll
        for (int nf = 0; nf < 4; nf++) {
            int cg = n0 + wn * 32 + nf * 8 + t4 * 2;
            if (cg < N) {
                float* p0 = C + (size_t)r0 * N + cg;
                p0[0] = acc[mf][nf][0];
                p0[1] = acc[mf][nf][1];
                float* p1 = p0 + (size_t)8 * N;
                p1[0] = acc[mf][nf][2];
                p1[1] = acc[mf][nf][3];
            }
        }
    }
}

__global__ __launch_bounds__(256) void gemm_in_kernel() {
    gemm_core(g_Ah, g_Bh, g_proj, BL, ProjD, Dm);
}

__global__ __launch_bounds__(256) void gemm_out_kernel(float* __restrict__ out) {
    gemm_core(g_Ah, g_Bh, out, BL, Dm, Inter);
}

// ---------------------------------------------------------------------------
// fp16 conversions
// ---------------------------------------------------------------------------
__global__ void round_x_kernel(const float* __restrict__ in, int n) {
    int i = blockIdx.x * blockDim.x + threadIdx.x;
    if (i >= n) return;
    g_Ah[i] = __float2half(in[i]);
}

__global__ void round_w_kernel(const float* __restrict__ in, int n) {
    int i = blockIdx.x * blockDim.x + threadIdx.x;
    if (i >= n) return;
    g_Bh[i] = __float2half(in[i]);
}

// ---------------------------------------------------------------------------
// Depthwise causal conv1d + SiLU (sliding window, 32 positions/thread)
// ---------------------------------------------------------------------------
__global__ __launch_bounds__(256) void conv_silu_kernel(const float* __restrict__ cw,
                                                        const float* __restrict__ cb) {
    int ch = blockIdx.x * 256 + threadIdx.x;
    int l0 = blockIdx.y * 32;
    int b  = blockIdx.z;
    const float* col = g_proj + (size_t)b * Ll * ProjD + Inter + ch;
    float w0 = cw[ch * KCONV + 0];
    float w1 = cw[ch * KCONV + 1];
    float w2 = cw[ch * KCONV + 2];
    float w3 = cw[ch * KCONV + 3];
    float bias = cb[ch];
    float xm3 = (l0 >= 3) ? col[(size_t)(l0 - 3) * ProjD] : 0.f;
    float xm2 = (l0 >= 2) ? col[(size_t)(l0 - 2) * ProjD] : 0.f;
    float xm1 = (l0 >= 1) ? col[(size_t)(l0 - 1) * ProjD] : 0.f;
    float* outp = g_conv + (size_t)(b * Ll + l0) * ConvD + ch;
#pragma unroll 4
    for (int i = 0; i < 32; i++) {
        float x0 = col[(size_t)(l0 + i) * ProjD];
        float acc = bias + w0 * xm3 + w1 * xm2 + w2 * xm1 + w3 * x0;
        outp[(size_t)i * ConvD] = siluf(acc);
        xm3 = xm2; xm2 = xm1; xm1 = x0;
    }
}

// ---------------------------------------------------------------------------
// Per-chunk inclusive cumsum of dt * A with fused softplus
// ---------------------------------------------------------------------------
__global__ void acum_kernel(const float* __restrict__ A_log,
                            const float* __restrict__ dt_bias) {
    int blk = blockIdx.x;
    int h = blk % Hh;
    int bc = blk / Hh;
    int b = bc / Nc, c = bc % Nc;
    int t = threadIdx.x;
    float A = -expf(A_log[h]);
    int bl = b * Ll + c * Ck + t;
    float raw = g_proj[(size_t)bl * ProjD + Inter + ConvD + h] + dt_bias[h];
    float dt = (raw > 20.f) ? raw : log1pf(expf(raw));
    g_dtv[(size_t)bl * Hh + h] = dt;
    float v = dt * A;
    __shared__ float s[Ck];
    s[t] = v;
    __syncthreads();
    for (int off = 1; off < Ck; off <<= 1) {
        float x = (t >= off) ? s[t - off] : 0.f;
        __syncthreads();
        s[t] += x;
        __syncthreads();
    }
    g_acum[(size_t)blk * Ck + t] = s[t];
}

// ---------------------------------------------------------------------------
// Gm[s,z] = sum_n C[s,n] * B[z,n] per (b,c), lower triangle (fp32, R11)
// ---------------------------------------------------------------------------
__global__ __launch_bounds__(256) void gm_kernel() {
    int bc = blockIdx.x;
    int sT = blockIdx.y, zT = blockIdx.z;
    if (zT > sT) return;
    int b = bc / Nc, c = bc % Nc;
    int rowbase = b * Ll + c * Ck;
    __shared__ __align__(16) float Cs[16][68];
    __shared__ __align__(16) float Bs[16][68];
    int tid = threadIdx.x;
    int ty = tid >> 4, tx = tid & 15;
    float acc[4][4];
#pragma unroll
    for (int i = 0; i < 4; i++)
#pragma unroll
        for (int j = 0; j < 4; j++) acc[i][j] = 0.f;

    int lrow = tid >> 2;
    int lcol = (tid & 3) * 4;

    for (int n0 = 0; n0 < Nn; n0 += 16) {
        float4 vc = ldg4(g_conv + (size_t)(rowbase + sT * 64 + lrow) * ConvD + Inter + Nn + n0 + lcol);
        float4 vb = ldg4(g_conv + (size_t)(rowbase + zT * 64 + lrow) * ConvD + Inter + n0 + lcol);
        Cs[lcol + 0][lrow] = vc.x; Cs[lcol + 1][lrow] = vc.y;
        Cs[lcol + 2][lrow] = vc.z; Cs[lcol + 3][lrow] = vc.w;
        Bs[lcol + 0][lrow] = vb.x; Bs[lcol + 1][lrow] = vb.y;
        Bs[lcol + 2][lrow] = vb.z; Bs[lcol + 3][lrow] = vb.w;
        __syncthreads();
#pragma unroll
        for (int kk = 0; kk < 16; kk++) {
            float4 rc = *(const float4*)&Cs[kk][ty * 4];
            float4 rb = *(const float4*)&Bs[kk][tx * 4];
            float rcv[4] = {rc.x, rc.y, rc.z, rc.w};
            float rbv[4] = {rb.x, rb.y, rb.z, rb.w};
#pragma unroll
            for (int i = 0; i < 4; i++)
#pragma unroll
                for (int j = 0; j < 4; j++) acc[i][j] += rcv[i] * rbv[j];
        }
        __syncthreads();
    }
#pragma unroll
    for (int i = 0; i < 4; i++) {
        int sg = sT * 64 + ty * 4 + i;
        float* pg = g_gm + ((size_t)bc * Ck + sg) * Ck + zT * 64 + tx * 4;
        *reinterpret_cast<float4*>(pg) = make_float4(acc[i][0], acc[i][1], acc[i][2], acc[i][3]);
    }
}

// ---------------------------------------------------------------------------
// states — fp32 (R11)
// ---------------------------------------------------------------------------
__global__ __launch_bounds__(256) void states_kernel() {
    int bc = blockIdx.x, h = blockIdx.y;
    int b = bc / Nc, c = bc % Nc;
    int tid = threadIdx.x;
    int ty = tid >> 4, tx = tid & 15;
    __shared__ __align__(16) float Hd[32][68];
    __shared__ __align__(16) float Bsm[32][132];
    const float* acumC = g_acum + ((size_t)bc * Hh + h) * Ck;
    float aLast = acumC[Ck - 1];
    int rowbase = b * Ll + c * Ck;
    float acc[4][8];
#pragma unroll
    for (int i = 0; i < 4; i++)
#pragma unroll
        for (int j = 0; j < 8; j++) acc[i][j] = 0.f;

    for (int l0 = 0; l0 < Ck; l0 += 32) {
        {
            int ll = tid >> 3;
            int p0 = (tid & 7) * 8;
            int l = rowbase + l0 + ll;
            float w = g_dtv[(size_t)l * Hh + h] * expf(aLast - acumC[l0 + ll]);
            const float* ph = g_conv + (size_t)l * ConvD + h * Pp + p0;
#pragma unroll
            for (int u = 0; u < 2; u++) {
                float4 v = ldg4(ph + u * 4);
                *reinterpret_cast<float4*>(&Hd[ll][p0 + u * 4]) =
                    make_float4(v.x * w, v.y * w, v.z * w, v.w * w);
            }
        }
        {
            int ll = tid >> 3;
            int n0v = (tid & 7) * 16;
            const float* pb = g_conv + (size_t)(rowbase + l0 + ll) * ConvD + Inter + n0v;
#pragma unroll
            for (int u = 0; u < 4; u++)
                *reinterpret_cast<float4*>(&Bsm[ll][n0v + u * 4]) = ldg4(pb + u * 4);
        }
        __syncthreads();
#pragma unroll 4
        for (int ll = 0; ll < 32; ll++) {
            float4 rh4 = *(const float4*)&Hd[ll][ty * 4];
            float4 rb0 = *(const float4*)&Bsm[ll][tx * 8];
            float4 rb1 = *(const float4*)&Bsm[ll][tx * 8 + 4];
            float rh[4] = {rh4.x, rh4.y, rh4.z, rh4.w};
            float rb[8] = {rb0.x, rb0.y, rb0.z, rb0.w, rb1.x, rb1.y, rb1.z, rb1.w};
#pragma unroll
            for (int i = 0; i < 4; i++)
#pragma unroll
                for (int j = 0; j < 8; j++) acc[i][j] += rh[i] * rb[j];
        }
        __syncthreads();
    }
    float* ps = g_states + ((size_t)bc * Hh + h) * Pp * Nn;
#pragma unroll
    for (int i = 0; i < 4; i++) {
        float* p = ps + (ty * 4 + i) * Nn + tx * 8;
        *reinterpret_cast<float4*>(p) = make_float4(acc[i][0], acc[i][1], acc[i][2], acc[i][3]);
        *reinterpret_cast<float4*>(p + 4) = make_float4(acc[i][4], acc[i][5], acc[i][6], acc[i][7]);
    }
}

// ---------------------------------------------------------------------------
// Inter-chunk recurrence
// ---------------------------------------------------------------------------
__global__ void prev_kernel() {
    int idx = blockIdx.x * blockDim.x + threadIdx.x;
    if (idx >= Bb * Hh * Pp * Nn) return;
    int n = idx % Nn;
    int p = (idx / Nn) % Pp;
    int h = (idx / (Nn * Pp)) % Hh;
    int b = idx / (Nn * Pp * Hh);
    float r = 0.f;
    for (int c = 0; c < Nc; c++) {
        size_t off = (((size_t)(b * Nc + c) * Hh + h) * Pp + p) * Nn + n;
        g_prev[off] = r;
        float zl = g_acum[((size_t)(b * Nc + c) * Hh + h) * Ck + (Ck - 1)];
        r = g_states[off] + expf(zl) * r;
    }
}

// ---------------------------------------------------------------------------
// FUSED Y_diag + Y_off + D residual — tensor-core version.
// Block = (bc, h, sT), 256 threads = 8 warps (4 m-tiles x 2 n-tiles).
// Phase 1: Ydiag via mma over fp16 Msh[s][z] (A) x Hsh[p][z] (B), acc fp32.
// Phase 2: Yoff via mma over fp16 Csh[l][n] x Psh[p][n].
// Single coalesced g_y write from register fragments.
// ---------------------------------------------------------------------------
__global__ __launch_bounds__(256) void ydiag_yoff_kernel(const float* __restrict__ Dv) {
    int bc = blockIdx.x;
    int h = blockIdx.y;
    int sT = blockIdx.z;
    int b = bc / Nc, c = bc % Nc;
    int tid = threadIdx.x;
    int lane = tid & 31;
    int warp = tid >> 5;
    int wm = warp >> 1;     // 0..3 (16 rows each)
    int wn = warp & 1;      // 0..1 (32 cols each)

    __shared__ __align__(16) char sb[34816];
    __half* Msh = (__half*)sb;            // [64][72]  A: [s][z]
    __half* Hsh = (__half*)(sb + 9216);   // [64][72]  B: [p][z]
    __half* Csh = (__half*)sb;            // [64][136] A: [l][n]
    __half* Psh = (__half*)(sb + 17408);  // [64][136] B: [p][n]
    __shared__ float sAc[64], zAc[64], ezs[64];

    const float* acumC = g_acum + ((size_t)bc * Hh + h) * Ck;
    if (tid < 64) sAc[tid] = acumC[sT * 64 + tid];
    int rowbase = b * Ll + c * Ck;
    int lbase = rowbase + sT * 64;

    const unsigned mbase = su32(Msh);
    const unsigned hbase = su32(Hsh);
    const int rA = lane & 15;
    const int cBy = (lane >> 4) << 4;

    float accd[4][4];
#pragma unroll
    for (int i = 0; i < 4; i++)
#pragma unroll
        for (int j = 0; j < 4; j++) accd[i][j] = 0.f;

    // ---- Phase 1: Y_diag over causal z-tiles ----
    for (int zT = 0; zT <= sT; zT++) {
        float M = acumC[zT * 64 + 63];
        if (tid < 64) {
            float az = acumC[zT * 64 + tid];
            zAc[tid] = az;
            ezs[tid] = expf(M - az);
        }
        {
            // Hsh[p][z] = hs[z][p]*dt[z] (transposed fp16 store)
            int zz = tid >> 2;
            int p0 = (tid & 3) * 16;
            int l = rowbase + zT * 64 + zz;
            float d = g_dtv[(size_t)l * Hh + h];
            const float* ph = g_conv + (size_t)l * ConvD + h * Pp + p0;
#pragma unroll
            for (int u = 0; u < 4; u++) {
                float4 v = ldg4(ph + u * 4);
                Hsh[(p0 + u * 4 + 0) * 72 + zz] = __float2half(v.x * d);
                Hsh[(p0 + u * 4 + 1) * 72 + zz] = __float2half(v.y * d);
                Hsh[(p0 + u * 4 + 2) * 72 + zz] = __float2half(v.z * d);
                Hsh[(p0 + u * 4 + 3) * 72 + zz] = __float2half(v.w * d);
            }
        }
        __syncthreads();
        {
            // Msh[s][z] build (fp16)
            int zz4 = (tid & 15) * 4;
            int ss4 = (tid >> 4) * 4;
            if (zT < sT) {
#pragma unroll
                for (int a = 0; a < 4; a++) {
                    int ss = ss4 + a;
                    int sg = sT * 64 + ss;
                    float es = expf(sAc[ss] - M);
                    float4 g = ldg4(g_gm + ((size_t)bc * Ck + sg) * Ck + zT * 64 + zz4);
                    float m0 = g.x * ezs[zz4 + 0] * es;
                    float m1 = g.y * ezs[zz4 + 1] * es;
                    float m2 = g.z * ezs[zz4 + 2] * es;
                    float m3 = g.w * ezs[zz4 + 3] * es;
                    *(half2*)&Msh[ss * 72 + zz4]     = __floats2half2_rn(m0, m1);
                    *(half2*)&Msh[ss * 72 + zz4 + 2] = __floats2half2_rn(m2, m3);
                }
            } else {
#pragma unroll
                for (int a = 0; a < 4; a++) {
                    int ss = ss4 + a;
                    int sg = sT * 64 + ss;
                    float as = sAc[ss];
                    float4 g = ldg4(g_gm + ((size_t)bc * Ck + sg) * Ck + zT * 64 + zz4);
                    float gv[4] = {g.x, g.y, g.z, g.w};
                    float mv[4];
#pragma unroll
                    for (int q = 0; q < 4; q++) {
                        int zz = zz4 + q;
                        mv[q] = ((zT * 64 + zz) <= sg) ? gv[q] * expf(as - zAc[zz]) : 0.f;
                    }
                    *(half2*)&Msh[ss * 72 + zz4]     = __floats2half2_rn(mv[0], mv[1]);
                    *(half2*)&Msh[ss * 72 + zz4 + 2] = __floats2half2_rn(mv[2], mv[3]);
                }
            }
        }
        __syncthreads();
        // mma: M=64(s) x N=64(p) x K=64(z), 4 ksteps
#pragma unroll
        for (int ks = 0; ks < 4; ks++) {
            unsigned colb = (unsigned)(ks * 32 + cBy);
            unsigned a[4];
            ldsm4(a[0], a[1], a[2], a[3], mbase + (wm * 16 + rA) * 144 + colb);
            unsigned bh[4][2];
#pragma unroll
            for (int nf2 = 0; nf2 < 2; nf2++) {
                unsigned rb = hbase + (wn * 32 + nf2 * 16 + rA) * 144 + colb;
                unsigned t0, t1, t2, t3;
                ldsm4(t0, t1, t2, t3, rb);
                bh[nf2 * 2][0] = t0; bh[nf2 * 2][1] = t2;
                bh[nf2 * 2 + 1][0] = t1; bh[nf2 * 2 + 1][1] = t3;
            }
#pragma unroll
            for (int nf = 0; nf < 4; nf++)
                mma16816(accd[nf], a, bh[nf]);
        }
        __syncthreads();
    }

    // ---- Phase 2: Y_off = C[l,n] * prev[p,n]^T, K=128 ----
    float acco[4][4];
#pragma unroll
    for (int i = 0; i < 4; i++)
#pragma unroll
        for (int j = 0; j < 4; j++) acco[i][j] = 0.f;

    const float* pprev = g_prev + ((size_t)bc * Hh + h) * Pp * Nn;
#pragma unroll
    for (int i = 0; i < 8; i++) {
        int q = tid + (i << 8);     // 0..2047
        int row = q >> 5;           // 0..63
        int c4 = (q & 31) * 4;      // 0..124
        float4 vc = ldg4(g_conv + (size_t)(lbase + row) * ConvD + Inter + Nn + c4);
        *(half2*)&Csh[row * 136 + c4]     = __floats2half2_rn(vc.x, vc.y);
        *(half2*)&Csh[row * 136 + c4 + 2] = __floats2half2_rn(vc.z, vc.w);
        float4 vp = ldg4(pprev + (size_t)row * Nn + c4);
        *(half2*)&Psh[row * 136 + c4]     = __floats2half2_rn(vp.x, vp.y);
        *(half2*)&Psh[row * 136 + c4 + 2] = __floats2half2_rn(vp.z, vp.w);
    }
    __syncthreads();
    const unsigned cbase2 = su32(Csh);
    const unsigned pbase2 = su32(Psh);
#pragma unroll
    for (int ks = 0; ks < 8; ks++) {
        unsigned colb = (unsigned)(ks * 32 + cBy);
        unsigned a[4];
        ldsm4(a[0], a[1], a[2], a[3], cbase2 + (wm * 16 + rA) * 272 + colb);
        unsigned bh[4][2];
#pragma unroll
        for (int nf2 = 0; nf2 < 2; nf2++) {
            unsigned rb = pbase2 + (wn * 32 + nf2 * 16 + rA) * 272 + colb;
            unsigned t0, t1, t2, t3;
            ldsm4(t0, t1, t2, t3, rb);
            bh[nf2 * 2][0] = t0; bh[nf2 * 2][1] = t2;
            bh[nf2 * 2 + 1][0] = t1; bh[nf2 * 2 + 1][1] = t3;
        }
#pragma unroll
        for (int nf = 0; nf < 4; nf++)
            mma16816(acco[nf], a, bh[nf]);
    }

    // ---- combine + single write (fragment layout) ----
    float Dh = Dv[h];
    int r0 = wm * 16 + (lane >> 2);
    int pb0 = wn * 32 + (lane & 3) * 2;
    float sd0 = expf(sAc[r0]);
    float sd1 = expf(sAc[r0 + 8]);
    int l0v = lbase + r0;
    int l1v = l0v + 8;
#pragma unroll
    for (int nf = 0; nf < 4; nf++) {
        int p = pb0 + nf * 8;
        float2 hv0 = *(const float2*)(g_conv + (size_t)l0v * ConvD + h * Pp + p);
        float2 o0;
        o0.x = accd[nf][0] + acco[nf][0] * sd0 + Dh * hv0.x;
        o0.y = accd[nf][1] + acco[nf][1] * sd0 + Dh * hv0.y;
        *(float2*)(g_y + (size_t)l0v * Inter + h * Pp + p) = o0;
        float2 hv1 = *(const float2*)(g_conv + (size_t)l1v * ConvD + h * Pp + p);
        float2 o1;
        o1.x = accd[nf][2] + acco[nf][2] * sd1 + Dh * hv1.x;
        o1.y = accd[nf][3] + acco[nf][3] * sd1 + Dh * hv1.y;
        *(float2*)(g_y + (size_t)l1v * Inter + h * Pp + p) = o1;
    }
}

// ---------------------------------------------------------------------------
// Gated RMSNorm; writes fp16-rounded y for the 1-pass out-proj
// ---------------------------------------------------------------------------
__global__ __launch_bounds__(256) void norm_kernel(const float* __restrict__ norm_w) {
    int row = blockIdx.x;
    int tid = threadIdx.x;
    const float* pg = g_proj + (size_t)row * ProjD;
    const float* py = g_y + (size_t)row * Inter;
    float f[8];
    float ss = 0.f;
#pragma unroll
    for (int u = 0; u < 8; u++) {
        int i = tid + u * 256;
        float g = pg[i];
        float v = py[i] * siluf(g);
        f[u] = v;
        ss += v * v;
    }
    __shared__ float red[8];
    int lane = tid & 31, wid = tid >> 5;
#pragma unroll
    for (int o = 16; o > 0; o >>= 1) ss += __shfl_xor_sync(0xffffffffu, ss, o);
    if (lane == 0) red[wid] = ss;
    __syncthreads();
    if (tid == 0) {
        float t = 0.f;
#pragma unroll
        for (int i = 0; i < 8; i++) t += red[i];
        red[0] = t;
    }
    __syncthreads();
    float rs = rsqrtf(red[0] / (float)Inter + 1e-6f);
#pragma unroll
    for (int u = 0; u < 8; u++) {
        int i = tid + u * 256;
        float v = f[u] * rs * norm_w[i];
        g_Ah[(size_t)row * Inter + i] = __float2half(v);
    }
}

// ---------------------------------------------------------------------------
// Launch
// ---------------------------------------------------------------------------
extern "C" void kernel_launch(void* const* d_in, const int* in_sizes, int n_in,
                              void* d_out, int out_size) {
    const float* x         = (const float*)d_in[0];
    const float* in_proj_w = (const float*)d_in[1];
    const float* conv_w    = (const float*)d_in[2];
    const float* conv_b    = (const float*)d_in[3];
    const float* dt_bias   = (const float*)d_in[4];
    const float* A_log     = (const float*)d_in[5];
    const float* Dv        = (const float*)d_in[6];
    const float* norm_w    = (const float*)d_in[7];
    const float* out_proj_w= (const float*)d_in[8];
    float* out = (float*)d_out;

    cudaFuncSetAttribute(gemm_in_kernel, cudaFuncAttributeMaxDynamicSharedMemorySize, GEMM_SMEM);
    cudaFuncSetAttribute(gemm_out_kernel, cudaFuncAttributeMaxDynamicSharedMemorySize, GEMM_SMEM);

    // 1) round x and in_proj_w to fp16
    {
        int n = BL * Dm;
        round_x_kernel<<<(n + 255) / 256, 256>>>(x, n);
        n = ProjD * Dm;
        round_w_kernel<<<(n + 255) / 256, 256>>>(in_proj_w, n);
    }
    // 2) in-projection GEMM (1-pass fp16)
    {
        dim3 grid((ProjD + 127) / 128, BL / 128);
        gemm_in_kernel<<<grid, 256, GEMM_SMEM>>>();
    }
    // 3) conv + SiLU
    {
        dim3 grid(ConvD / 256, Ll / 32, Bb);
        conv_silu_kernel<<<grid, 256>>>(conv_w, conv_b);
    }
    // 4) cumsum of dt*A (fused softplus)
    acum_kernel<<<Bb * Nc * Hh, Ck>>>(A_log, dt_bias);
    // 5) Gm = C B^T
    {
        dim3 grid(Bb * Nc, Ck / 64, Ck / 64);
        gm_kernel<<<grid, 256>>>();
    }
    // 6) states
    {
        dim3 grid(Bb * Nc, Hh);
        states_kernel<<<grid, 256>>>();
    }
    // 7) inter-chunk recurrence
    {
        int total = Bb * Hh * Pp * Nn;
        prev_kernel<<<(total + 255) / 256, 256>>>();
    }
    // 8) fused Y_diag + Y_off + D residual (tensor cores)
    {
        dim3 grid(Bb * Nc, Hh, Ck / 64);
        ydiag_yoff_kernel<<<grid, 256>>>(Dv);
    }
    // 9) gated RMSNorm (writes fp16 y)
    norm_kernel<<<BL, 256>>>(norm_w);
    // 10) round out_proj_w to fp16
    {
        int n = Dm * Inter;
        round_w_kernel<<<(n + 255) / 256, 256>>>(out_proj_w, n);
    }
    // 11) out-projection GEMM (1-pass fp16)
    {
        dim3 grid(Dm / 128, BL / 128);
        gemm_out_kernel<<<grid, 256, GEMM_SMEM>>>(out);
    }
    (void)in_sizes; (void)n_in; (void)out_size;
}